// round 14
// baseline (speedup 1.0000x reference)
#include <cuda_runtime.h>
#include <cuda_fp16.h>
#include <cstdint>

#define NB 2
#define SEQ 2048
#define EMB 1024
#define NHEADS 16
#define NROWS (NB * SEQ)

// Scratch (__device__ globals per allocation rules)
__device__ __half g_wh[EMB * EMB];          // folded Wv/Wo fp16: [k'][n]
__device__ __half g_vh[NROWS * EMB];        // value as fp16
__device__ __half g_vch[NROWS * EMB];       // Vc = value @ Wcomb, fp16

// ---------------------------------------------------------------------------
__device__ __forceinline__ void mma_f16(float c[4],
                                        uint32_t a0, uint32_t a1, uint32_t a2, uint32_t a3,
                                        uint32_t b0, uint32_t b1) {
    asm volatile(
        "mma.sync.aligned.m16n8k16.row.col.f32.f16.f16.f32 "
        "{%0,%1,%2,%3}, {%4,%5,%6,%7}, {%8,%9}, {%0,%1,%2,%3};"
        : "+f"(c[0]), "+f"(c[1]), "+f"(c[2]), "+f"(c[3])
        : "r"(a0), "r"(a1), "r"(a2), "r"(a3), "r"(b0), "r"(b1));
}

__device__ __forceinline__ void ldsm_x4(uint32_t& r0, uint32_t& r1,
                                        uint32_t& r2, uint32_t& r3, uint32_t addr) {
    asm volatile("ldmatrix.sync.aligned.m8n8.x4.shared.b16 {%0,%1,%2,%3}, [%4];"
                 : "=r"(r0), "=r"(r1), "=r"(r2), "=r"(r3) : "r"(addr));
}
__device__ __forceinline__ void ldsm_x4_t(uint32_t& r0, uint32_t& r1,
                                          uint32_t& r2, uint32_t& r3, uint32_t addr) {
    asm volatile("ldmatrix.sync.aligned.m8n8.x4.trans.shared.b16 {%0,%1,%2,%3}, [%4];"
                 : "=r"(r0), "=r"(r1), "=r"(r2), "=r"(r3) : "r"(addr));
}

__device__ __forceinline__ void cp16(uint32_t s, const void* g) {
    asm volatile("cp.async.cg.shared.global [%0], [%1], 16;" :: "r"(s), "l"(g));
}
__device__ __forceinline__ void cp_commit() { asm volatile("cp.async.commit_group;"); }
__device__ __forceinline__ void cp_wait0()  { asm volatile("cp.async.wait_group 0;"); }
__device__ __forceinline__ void cp_wait1()  { asm volatile("cp.async.wait_group 1;"); }
__device__ __forceinline__ void cp_wait2()  { asm volatile("cp.async.wait_group 2;"); }

// ---------------------------------------------------------------------------
// Prep: blocks [0,256) wcomb -> g_wh;  blocks [256,2304) value -> fp16
// ---------------------------------------------------------------------------
#define PREP_SMEM (2 * 64 * 68 * 4)

__global__ __launch_bounds__(256) void prep_kernel(
    const float* __restrict__ value,
    const float* __restrict__ Wv, const float* __restrict__ Wo)
{
    extern __shared__ char psm[];
    const int b = blockIdx.x;
    const int tid = threadIdx.x;

    if (b < 256) {
        float (*sWv)[68]  = (float(*)[68])psm;
        float (*sWoT)[68] = (float(*)[68])(psm + 64 * 68 * 4);
        const int h = b >> 4;
        const int n0 = (b & 15) * 64;

        for (int i = tid; i < 4096; i += 256) {
            int d = i >> 6, r = i & 63;
            sWv[d][r] = Wv[i];
        }
        for (int i = tid; i < 4096; i += 256) {
            int c = i >> 6, d = i & 63;
            sWoT[d][c] = Wo[(long)(n0 + c) * EMB + h * 64 + d];
        }
        __syncthreads();

        const int tr = (tid >> 4) * 4, tc = (tid & 15) * 4;
        float acc[4][4];
#pragma unroll
        for (int i = 0; i < 4; i++)
#pragma unroll
            for (int j = 0; j < 4; j++) acc[i][j] = 0.f;
#pragma unroll
        for (int d = 0; d < 64; d++) {
            float4 av = *(const float4*)&sWv[d][tr];
            float4 bv = *(const float4*)&sWoT[d][tc];
            float a[4] = {av.x, av.y, av.z, av.w};
            float bb[4] = {bv.x, bv.y, bv.z, bv.w};
#pragma unroll
            for (int i = 0; i < 4; i++)
#pragma unroll
                for (int j = 0; j < 4; j++) acc[i][j] += a[i] * bb[j];
        }
#pragma unroll
        for (int i = 0; i < 4; i++) {
            __half2 h0 = __floats2half2_rn(acc[i][0], acc[i][1]);
            __half2 h1 = __floats2half2_rn(acc[i][2], acc[i][3]);
            uint2 w = make_uint2(*(uint32_t*)&h0, *(uint32_t*)&h1);
            *(uint2*)(g_wh + (long)(h * 64 + tr + i) * EMB + n0 + tc) = w;
        }
    } else {
        long i0 = (long)(b - 256) * 512 + tid;
#pragma unroll
        for (int u = 0; u < 2; u++) {
            long i = i0 + u * 256;
            float4 v = ((const float4*)value)[i];
            __half2 h0 = __floats2half2_rn(v.x, v.y);
            __half2 h1 = __floats2half2_rn(v.z, v.w);
            ((uint2*)g_vh)[i] = make_uint2(*(uint32_t*)&h0, *(uint32_t*)&h1);
        }
    }
}

// ---------------------------------------------------------------------------
// Vc GEMM (proven R11 config): block 128x128, BK=32, NSTG=4, 256 thr, 2 CTA/SM.
// A smem: 128 rows x 40 halves (pad). B smem: [32][128], chunk swizzle cc^(r&7).
// ---------------------------------------------------------------------------
#define BM 128
#define BK 32
#define VC_NSTG 4
#define A_BYTES (BM * 40 * 2)
#define VC_B_BYTES (BK * 128 * 2)
#define VC_SMEM (VC_NSTG * (A_BYTES + VC_B_BYTES))   // 73728

__global__ __launch_bounds__(256, 2) void vc_gemm_kernel()
{
    extern __shared__ char smh[];
    uint32_t sA = (uint32_t)__cvta_generic_to_shared(smh);
    uint32_t sB = sA + VC_NSTG * A_BYTES;

    const int tid = threadIdx.x;
    const int wid = tid >> 5, lane = tid & 31;
    const int gid = lane >> 2, tig = lane & 3;
    const int wm = (wid >> 2) * 64;
    const int wn = (wid & 3) * 32;

    const int e0 = blockIdx.x * 128;
    const int row0 = blockIdx.y * BM;

    const __half* Ab = g_vh + (long)row0 * EMB;
    const __half* Bb = g_wh + e0;

    const int lrow = lane & 15;
    const int lk8 = (lane & 16) >> 1;
    const int bhi = (lane >> 4) & 1;

    uint32_t aoff[4];
#pragma unroll
    for (int mt = 0; mt < 4; mt++)
        aoff[mt] = (uint32_t)((wm + mt * 16 + lrow) * 40 + lk8) * 2;

    float acc[4][4][4];
#pragma unroll
    for (int a = 0; a < 4; a++)
#pragma unroll
        for (int b = 0; b < 4; b++)
#pragma unroll
            for (int c = 0; c < 4; c++) acc[a][b][c] = 0.f;

    auto load_tiles = [&](int k0, int st) {
#pragma unroll
        for (int u = 0; u < 2; u++) {
            int ch = tid + u * 256;                 // A: 512 chunks
            int r = ch >> 2, cc = ch & 3;
            cp16(sA + (uint32_t)(st * A_BYTES) + (uint32_t)(r * 40 + cc * 8) * 2,
                 Ab + (long)r * EMB + k0 + cc * 8);
        }
#pragma unroll
        for (int u = 0; u < 2; u++) {
            int ch = tid + u * 256;                 // B: 512 chunks (32 x 16)
            int r = ch >> 4, cc = ch & 15;
            cp16(sB + (uint32_t)(st * VC_B_BYTES) +
                     (uint32_t)(r * 128 + ((cc ^ (r & 7)) * 8)) * 2,
                 Bb + (long)(k0 + r) * EMB + cc * 8);
        }
        cp_commit();
    };

    load_tiles(0, 0);
    load_tiles(BK, 1);
    load_tiles(2 * BK, 2);

    const int nIter = EMB / BK;
    for (int i = 0; i < nIter; i++) {
        const int rem = nIter - 1 - i;
        if (rem >= 2) cp_wait2();
        else if (rem == 1) cp_wait1();
        else cp_wait0();
        __syncthreads();
        if (i + 3 < nIter) load_tiles((i + 3) * BK, (i + 3) % VC_NSTG);

        const int st = i % VC_NSTG;
        const uint32_t aS = sA + (uint32_t)(st * A_BYTES);
        const uint32_t bS = sB + (uint32_t)(st * VC_B_BYTES);

#pragma unroll
        for (int ks = 0; ks < 2; ks++) {
            const int kb = ks * 16;
            uint32_t a[4][4], br[2][4];
#pragma unroll
            for (int mt = 0; mt < 4; mt++)
                ldsm_x4(a[mt][0], a[mt][1], a[mt][2], a[mt][3],
                        aS + aoff[mt] + kb * 2);
#pragma unroll
            for (int nt2 = 0; nt2 < 2; nt2++) {
                int krow = kb + lrow;
                int nc = ((wn + nt2 * 16) >> 3) + bhi;
                int cs = nc ^ (krow & 7);
                ldsm_x4_t(br[nt2][0], br[nt2][1], br[nt2][2], br[nt2][3],
                          bS + (uint32_t)(krow * 128 + cs * 8) * 2);
            }
#pragma unroll
            for (int mt = 0; mt < 4; mt++)
#pragma unroll
                for (int nt = 0; nt < 4; nt++) {
                    int nt2 = nt >> 1, pr = (nt & 1) * 2;
                    mma_f16(acc[mt][nt], a[mt][0], a[mt][1], a[mt][2], a[mt][3],
                            br[nt2][pr], br[nt2][pr + 1]);
                }
        }
    }

#pragma unroll
    for (int mt = 0; mt < 4; mt++) {
        int r0a = row0 + wm + mt * 16 + gid;
#pragma unroll
        for (int nt = 0; nt < 4; nt++) {
            int col = e0 + wn + nt * 8 + 2 * tig;
            __half2 h0 = __floats2half2_rn(acc[mt][nt][0], acc[mt][nt][1]);
            __half2 h1 = __floats2half2_rn(acc[mt][nt][2], acc[mt][nt][3]);
            *(__half2*)(g_vch + (long)r0a * EMB + col) = h0;
            *(__half2*)(g_vch + (long)(r0a + 8) * EMB + col) = h1;
        }
    }
}

// ---------------------------------------------------------------------------
// Masked GEMM with INLINE mask conversion + inline counts.
// out[q][e] = (1/cnt_q) * sum_k (mask[q,k]==0) * Vc[k][e] + bo[e]
// Block 128x256, 512 threads (2m x 8n warps), BK=32, NSTG=4.
// Aint smem: raw int32 mask tiles (128 x 32 ints, rows padded to 36 ints).
// Converted each iter into a double-buffered fp16 A tile (128 x 40 halves).
// Per-row zero counts accumulate in registers during conversion.
// ---------------------------------------------------------------------------
#define MSK_NSTG 4
#define AI_BYTES (128 * 36 * 4)                    // 18432
#define MS_B_BYTES (BK * 256 * 2)                  // 16384
#define AF_BYTES (128 * 40 * 2)                    // 10240
#define MS_SMEM (MSK_NSTG * (AI_BYTES + MS_B_BYTES) + 2 * AF_BYTES + 512)

__global__ __launch_bounds__(512, 1) void masked_gemm_kernel(
    const int* __restrict__ mask, const float* __restrict__ bo, float* __restrict__ Y)
{
    extern __shared__ char smh[];
    uint32_t sAi = (uint32_t)__cvta_generic_to_shared(smh);
    uint32_t sB  = sAi + MSK_NSTG * AI_BYTES;
    uint32_t sAf = sB + MSK_NSTG * MS_B_BYTES;
    char* afPtr  = smh + MSK_NSTG * (AI_BYTES + MS_B_BYTES);
    float* s_inv = (float*)(smh + MSK_NSTG * (AI_BYTES + MS_B_BYTES) + 2 * AF_BYTES);

    const int tid = threadIdx.x;
    const int wid = tid >> 5, lane = tid & 31;
    const int gid = lane >> 2, tig = lane & 3;
    const int wm = (wid >> 3) * 64;
    const int wn = (wid & 7) * 32;

    const int e0 = blockIdx.x * 256;
    const int row0 = blockIdx.y * BM;
    const int n = row0 / SEQ;

    const int* Am = mask + (long)n * SEQ * SEQ + (long)(row0 % SEQ) * SEQ;
    const __half* Bb = g_vch + (long)n * SEQ * EMB + e0;

    const int lrow = lane & 15;
    const int lk8 = (lane & 16) >> 1;
    const int bhi = (lane >> 4) & 1;

    uint32_t aoff[4];
#pragma unroll
    for (int mt = 0; mt < 4; mt++)
        aoff[mt] = (uint32_t)((wm + mt * 16 + lrow) * 40 + lk8) * 2;

    // convert-ownership: thread owns row crow, ints cK..cK+7 of each tile
    const int crow = tid >> 2;
    const int cK = (tid & 3) * 8;

    float acc[4][4][4];
#pragma unroll
    for (int a = 0; a < 4; a++)
#pragma unroll
        for (int b = 0; b < 4; b++)
#pragma unroll
            for (int c = 0; c < 4; c++) acc[a][b][c] = 0.f;
    int cnt = 0;

    auto load_tiles = [&](int k0, int st) {
#pragma unroll
        for (int u = 0; u < 2; u++) {
            int ch = tid + u * 512;                 // Aint: 1024 chunks (128 x 8)
            int r = ch >> 3, cc = ch & 7;
            cp16(sAi + (uint32_t)(st * AI_BYTES) + (uint32_t)(r * 36 + cc * 4) * 4,
                 Am + (long)r * SEQ + k0 + cc * 4);
        }
#pragma unroll
        for (int u = 0; u < 2; u++) {
            int ch = tid + u * 512;                 // B: 1024 chunks (32 x 32)
            int r = ch >> 5, cc = ch & 31;
            cp16(sB + (uint32_t)(st * MS_B_BYTES) +
                     (uint32_t)(r * 256 + ((cc ^ (r & 7)) * 8)) * 2,
                 Bb + (long)(k0 + r) * EMB + cc * 8);
        }
        cp_commit();
    };

    load_tiles(0, 0);
    load_tiles(BK, 1);
    load_tiles(2 * BK, 2);

    const uint32_t ONE = 0x3C00u;
    const int nIter = SEQ / BK;
    for (int i = 0; i < nIter; i++) {
        const int rem = nIter - 1 - i;
        if (rem >= 2) cp_wait2();
        else if (rem == 1) cp_wait1();
        else cp_wait0();
        __syncthreads();                            // sync1: stage data visible
        if (i + 3 < nIter) load_tiles((i + 3) * BK, (i + 3) % MSK_NSTG);

        const int st = i % MSK_NSTG;
        const int buf = i & 1;

        // convert int32 mask tile -> fp16 A tile (and count zeros)
        {
            const int* ai = (const int*)(smh + st * AI_BYTES) + crow * 36 + cK;
            int4 m0 = *(const int4*)ai;
            int4 m1 = *(const int4*)(ai + 4);
            uint32_t h0 = ((m0.x == 0) ? ONE : 0u) | (((m0.y == 0) ? ONE : 0u) << 16);
            uint32_t h1 = ((m0.z == 0) ? ONE : 0u) | (((m0.w == 0) ? ONE : 0u) << 16);
            uint32_t h2 = ((m1.x == 0) ? ONE : 0u) | (((m1.y == 0) ? ONE : 0u) << 16);
            uint32_t h3 = ((m1.z == 0) ? ONE : 0u) | (((m1.w == 0) ? ONE : 0u) << 16);
            cnt += (m0.x == 0) + (m0.y == 0) + (m0.z == 0) + (m0.w == 0)
                 + (m1.x == 0) + (m1.y == 0) + (m1.z == 0) + (m1.w == 0);
            *(uint4*)(afPtr + buf * AF_BYTES + (crow * 40 + cK) * 2) =
                make_uint4(h0, h1, h2, h3);
        }
        __syncthreads();                            // sync2: fp16 A tile ready

        const uint32_t aS = sAf + (uint32_t)(buf * AF_BYTES);
        const uint32_t bS = sB + (uint32_t)(st * MS_B_BYTES);

#pragma unroll
        for (int ks = 0; ks < 2; ks++) {
            const int kb = ks * 16;
            uint32_t a[4][4], br[2][4];
#pragma unroll
            for (int mt = 0; mt < 4; mt++)
                ldsm_x4(a[mt][0], a[mt][1], a[mt][2], a[mt][3],
                        aS + aoff[mt] + kb * 2);
#pragma unroll
            for (int nt2 = 0; nt2 < 2; nt2++) {
                int krow = kb + lrow;
                int nc = ((wn + nt2 * 16) >> 3) + bhi;
                int cs = nc ^ (krow & 7);
                ldsm_x4_t(br[nt2][0], br[nt2][1], br[nt2][2], br[nt2][3],
                          bS + (uint32_t)(krow * 256 + cs * 8) * 2);
            }
#pragma unroll
            for (int mt = 0; mt < 4; mt++)
#pragma unroll
                for (int nt = 0; nt < 4; nt++) {
                    int nt2 = nt >> 1, pr = (nt & 1) * 2;
                    mma_f16(acc[mt][nt], a[mt][0], a[mt][1], a[mt][2], a[mt][3],
                            br[nt2][pr], br[nt2][pr + 1]);
                }
        }
    }

    // reduce counts (threads 4r..4r+3 are consecutive lanes) -> s_inv
    cnt += __shfl_xor_sync(0xffffffffu, cnt, 1);
    cnt += __shfl_xor_sync(0xffffffffu, cnt, 2);
    if ((tid & 3) == 0) s_inv[crow] = 1.0f / (float)cnt;
    __syncthreads();

#pragma unroll
    for (int mt = 0; mt < 4; mt++) {
        int rloc = wm + mt * 16 + gid;
        int r0a = row0 + rloc;
        float s0 = s_inv[rloc];
        float s1 = s_inv[rloc + 8];
#pragma unroll
        for (int nt = 0; nt < 4; nt++) {
            int col = e0 + wn + nt * 8 + 2 * tig;
            float b0v = bo[col], b1v = bo[col + 1];
            float2 v0 = make_float2(acc[mt][nt][0] * s0 + b0v, acc[mt][nt][1] * s0 + b1v);
            float2 v1 = make_float2(acc[mt][nt][2] * s1 + b0v, acc[mt][nt][3] * s1 + b1v);
            *(float2*)(Y + (long)r0a * EMB + col) = v0;
            *(float2*)(Y + (long)(r0a + 8) * EMB + col) = v1;
        }
    }
}

// ---------------------------------------------------------------------------
extern "C" void kernel_launch(void* const* d_in, const int* in_sizes, int n_in,
                              void* d_out, int out_size)
{
    const float* value = (const float*)d_in[0];
    // key/query/Wk/Wq unused: masked_fill(+1e20) before softmax forces all
    // unmasked scores to underflow; output is the masked average of projected V.
    const int*   mask  = (const int*)d_in[3];
    const float* Wv    = (const float*)d_in[4];
    const float* Wo    = (const float*)d_in[7];
    const float* bo    = (const float*)d_in[8];
    float* out = (float*)d_out;

    cudaFuncSetAttribute(prep_kernel,
                         cudaFuncAttributeMaxDynamicSharedMemorySize, PREP_SMEM);
    cudaFuncSetAttribute(vc_gemm_kernel,
                         cudaFuncAttributeMaxDynamicSharedMemorySize, VC_SMEM);
    cudaFuncSetAttribute(masked_gemm_kernel,
                         cudaFuncAttributeMaxDynamicSharedMemorySize, MS_SMEM);

    prep_kernel<<<2304, 256, PREP_SMEM>>>(value, Wv, Wo);
    {
        dim3 grid(EMB / 128, NROWS / BM);           // (8, 32)
        vc_gemm_kernel<<<grid, 256, VC_SMEM>>>();
    }
    {
        dim3 grid(EMB / 256, NROWS / BM);           // (4, 32)
        masked_gemm_kernel<<<grid, 512, MS_SMEM>>>(mask, bo, out);
    }
}

// round 15
// speedup vs baseline: 1.0585x; 1.0585x over previous
#include <cuda_runtime.h>
#include <cuda_fp16.h>
#include <cstdint>

#define NB 2
#define SEQ 2048
#define EMB 1024
#define NHEADS 16
#define NROWS (NB * SEQ)

// Scratch (__device__ globals per allocation rules)
__device__ __half g_wh[EMB * EMB];          // folded Wv/Wo fp16: [k'][n]
__device__ __half g_vch[NROWS * EMB];       // Vc = value @ Wcomb, fp16
__device__ __half g_afh[(long)NROWS * SEQ]; // binary mask fp16: 1.0 where mask==0
__device__ float  g_invcnt[NROWS];          // 1 / (# zeros in row), fp32

// ---------------------------------------------------------------------------
__device__ __forceinline__ void mma_f16(float c[4],
                                        uint32_t a0, uint32_t a1, uint32_t a2, uint32_t a3,
                                        uint32_t b0, uint32_t b1) {
    asm volatile(
        "mma.sync.aligned.m16n8k16.row.col.f32.f16.f16.f32 "
        "{%0,%1,%2,%3}, {%4,%5,%6,%7}, {%8,%9}, {%0,%1,%2,%3};"
        : "+f"(c[0]), "+f"(c[1]), "+f"(c[2]), "+f"(c[3])
        : "r"(a0), "r"(a1), "r"(a2), "r"(a3), "r"(b0), "r"(b1));
}

__device__ __forceinline__ void ldsm_x4(uint32_t& r0, uint32_t& r1,
                                        uint32_t& r2, uint32_t& r3, uint32_t addr) {
    asm volatile("ldmatrix.sync.aligned.m8n8.x4.shared.b16 {%0,%1,%2,%3}, [%4];"
                 : "=r"(r0), "=r"(r1), "=r"(r2), "=r"(r3) : "r"(addr));
}
__device__ __forceinline__ void ldsm_x4_t(uint32_t& r0, uint32_t& r1,
                                          uint32_t& r2, uint32_t& r3, uint32_t addr) {
    asm volatile("ldmatrix.sync.aligned.m8n8.x4.trans.shared.b16 {%0,%1,%2,%3}, [%4];"
                 : "=r"(r0), "=r"(r1), "=r"(r2), "=r"(r3) : "r"(addr));
}

__device__ __forceinline__ void cp16(uint32_t s, const void* g) {
    asm volatile("cp.async.cg.shared.global [%0], [%1], 16;" :: "r"(s), "l"(g));
}
__device__ __forceinline__ void cp_commit() { asm volatile("cp.async.commit_group;"); }
__device__ __forceinline__ void cp_wait0()  { asm volatile("cp.async.wait_group 0;"); }
__device__ __forceinline__ void cp_wait1()  { asm volatile("cp.async.wait_group 1;"); }
__device__ __forceinline__ void cp_wait2()  { asm volatile("cp.async.wait_group 2;"); }

// ---------------------------------------------------------------------------
// Prep kernel (R11 shape minus cvtv):
//  blocks [0,256):        wcomb -> g_wh
//  blocks [256,4352):     mask row -> g_afh + invcnt (1 row/block)
// ---------------------------------------------------------------------------
#define PREP_SMEM (2 * 64 * 68 * 4)
#define PREP_GRID 4352

__global__ __launch_bounds__(256) void prep_kernel(
    const int* __restrict__ mask,
    const float* __restrict__ Wv, const float* __restrict__ Wo)
{
    extern __shared__ char psm[];
    const int b = blockIdx.x;
    const int tid = threadIdx.x;

    if (b < 256) {
        float (*sWv)[68]  = (float(*)[68])psm;
        float (*sWoT)[68] = (float(*)[68])(psm + 64 * 68 * 4);
        const int h = b >> 4;
        const int n0 = (b & 15) * 64;

        for (int i = tid; i < 4096; i += 256) {
            int d = i >> 6, r = i & 63;
            sWv[d][r] = Wv[i];
        }
        for (int i = tid; i < 4096; i += 256) {
            int c = i >> 6, d = i & 63;
            sWoT[d][c] = Wo[(long)(n0 + c) * EMB + h * 64 + d];
        }
        __syncthreads();

        const int tr = (tid >> 4) * 4, tc = (tid & 15) * 4;
        float acc[4][4];
#pragma unroll
        for (int i = 0; i < 4; i++)
#pragma unroll
            for (int j = 0; j < 4; j++) acc[i][j] = 0.f;
#pragma unroll
        for (int d = 0; d < 64; d++) {
            float4 av = *(const float4*)&sWv[d][tr];
            float4 bv = *(const float4*)&sWoT[d][tc];
            float a[4] = {av.x, av.y, av.z, av.w};
            float bb[4] = {bv.x, bv.y, bv.z, bv.w};
#pragma unroll
            for (int i = 0; i < 4; i++)
#pragma unroll
                for (int j = 0; j < 4; j++) acc[i][j] += a[i] * bb[j];
        }
#pragma unroll
        for (int i = 0; i < 4; i++) {
            __half2 h0 = __floats2half2_rn(acc[i][0], acc[i][1]);
            __half2 h1 = __floats2half2_rn(acc[i][2], acc[i][3]);
            uint2 w = make_uint2(*(uint32_t*)&h0, *(uint32_t*)&h1);
            *(uint2*)(g_wh + (long)(h * 64 + tr + i) * EMB + n0 + tc) = w;
        }
    } else {
        int* ws = (int*)psm;
        const int row = b - 256;
        const long base = (long)row * SEQ;
        const int4* mp = (const int4*)(mask + base);

        int4 a = mp[tid];
        int4 bb = mp[tid + 256];
        int c = (a.x == 0) + (a.y == 0) + (a.z == 0) + (a.w == 0)
              + (bb.x == 0) + (bb.y == 0) + (bb.z == 0) + (bb.w == 0);
#pragma unroll
        for (int off = 16; off > 0; off >>= 1)
            c += __shfl_down_sync(0xffffffffu, c, off);
        if ((tid & 31) == 0) ws[tid >> 5] = c;
        __syncthreads();
        if (tid == 0) {
            int t = 0;
#pragma unroll
            for (int i = 0; i < 8; i++) t += ws[i];
            g_invcnt[row] = 1.0f / (float)t;
        }

        const uint32_t ONE = 0x3C00u;
        uint2 w0, w1;
        w0.x = ((a.x == 0) ? ONE : 0u) | (((a.y == 0) ? ONE : 0u) << 16);
        w0.y = ((a.z == 0) ? ONE : 0u) | (((a.w == 0) ? ONE : 0u) << 16);
        w1.x = ((bb.x == 0) ? ONE : 0u) | (((bb.y == 0) ? ONE : 0u) << 16);
        w1.y = ((bb.z == 0) ? ONE : 0u) | (((bb.w == 0) ? ONE : 0u) << 16);
        *(uint2*)(g_afh + base + tid * 4) = w0;
        *(uint2*)(g_afh + base + 1024 + tid * 4) = w1;
    }
}

// ---------------------------------------------------------------------------
// Vc GEMM, fp32-A variant: Vc = value(fp32) @ g_wh.
// Block 128x128, BK=32, 256 threads, 8 warps (2m x 4n), NSTG=3, 2 CTAs/SM.
// A staged as raw fp32 (rows of 32 floats, 4-float-chunk xor swizzle), then
// converted per-iter into a double-buffered fp16 tile (rows pad 40 halves)
// for the standard ldsm path. B (g_wh) as in R11.
// ---------------------------------------------------------------------------
#define BM 128
#define BK 32
#define VC_NSTG 3
#define AF32_BYTES (BM * BK * 4)                 // 16384
#define VC_B_BYTES (BK * 128 * 2)                // 8192
#define AF16_BYTES (BM * 40 * 2)                 // 10240
#define VC_SMEM (VC_NSTG * (AF32_BYTES + VC_B_BYTES) + 2 * AF16_BYTES)  // 94208

__global__ __launch_bounds__(256, 2) void vc_gemm_kernel(const float* __restrict__ value)
{
    extern __shared__ char smh[];
    uint32_t sA32 = (uint32_t)__cvta_generic_to_shared(smh);
    uint32_t sB   = sA32 + VC_NSTG * AF32_BYTES;
    uint32_t sA16 = sB + VC_NSTG * VC_B_BYTES;
    char* a16Ptr  = smh + VC_NSTG * (AF32_BYTES + VC_B_BYTES);

    const int tid = threadIdx.x;
    const int wid = tid >> 5, lane = tid & 31;
    const int gid = lane >> 2, tig = lane & 3;
    const int wm = (wid >> 2) * 64;
    const int wn = (wid & 3) * 32;

    const int e0 = blockIdx.x * 128;
    const int row0 = blockIdx.y * BM;

    const float* Ab = value + (long)row0 * EMB;
    const __half* Bb = g_wh + e0;

    const int lrow = lane & 15;
    const int lk8 = (lane & 16) >> 1;
    const int bhi = (lane >> 4) & 1;

    uint32_t aoff[4];
#pragma unroll
    for (int mt = 0; mt < 4; mt++)
        aoff[mt] = (uint32_t)((wm + mt * 16 + lrow) * 40 + lk8) * 2;

    // convert ownership: row crow, 16 cols starting at half*16
    const int crow = tid >> 1;
    const int half = tid & 1;

    float acc[4][4][4];
#pragma unroll
    for (int a = 0; a < 4; a++)
#pragma unroll
        for (int b = 0; b < 4; b++)
#pragma unroll
            for (int c = 0; c < 4; c++) acc[a][b][c] = 0.f;

    auto load_tiles = [&](int k0, int st) {
#pragma unroll
        for (int u = 0; u < 4; u++) {
            int ch = tid + u * 256;                // A: 1024 chunks (128 rows x 8)
            int r = ch >> 3, cc = ch & 7;
            cp16(sA32 + (uint32_t)(st * AF32_BYTES) +
                     (uint32_t)(r * 32 + ((cc ^ (r & 7)) * 4)) * 4,
                 Ab + (long)r * EMB + k0 + cc * 4);
        }
#pragma unroll
        for (int u = 0; u < 2; u++) {
            int ch = tid + u * 256;                // B: 512 chunks (32 x 16)
            int r = ch >> 4, cc = ch & 15;
            cp16(sB + (uint32_t)(st * VC_B_BYTES) +
                     (uint32_t)(r * 128 + ((cc ^ (r & 7)) * 8)) * 2,
                 Bb + (long)(k0 + r) * EMB + cc * 8);
        }
        cp_commit();
    };

    load_tiles(0, 0);
    load_tiles(BK, 1);

    const int nIter = EMB / BK;
    for (int i = 0; i < nIter; i++) {
        if (i < nIter - 1) cp_wait1(); else cp_wait0();
        __syncthreads();                           // sync1: fp32/B stage ready
        if (i + 2 < nIter) load_tiles((i + 2) * BK, (i + 2) % VC_NSTG);

        const int st = i % VC_NSTG;
        const int buf = i & 1;

        // convert fp32 A tile -> fp16 ldsm tile
        {
            const float* a32 = (const float*)(smh + st * AF32_BYTES) + crow * 32;
            uint32_t hh[8];
#pragma unroll
            for (int j = 0; j < 4; j++) {
                int lc = half * 4 + j;
                int pc = lc ^ (crow & 7);
                float4 v = *(const float4*)&a32[pc * 4];
                __half2 p0 = __floats2half2_rn(v.x, v.y);
                __half2 p1 = __floats2half2_rn(v.z, v.w);
                hh[j * 2] = *(uint32_t*)&p0;
                hh[j * 2 + 1] = *(uint32_t*)&p1;
            }
            char* dst = a16Ptr + buf * AF16_BYTES + (crow * 40 + half * 16) * 2;
            *(uint4*)dst = make_uint4(hh[0], hh[1], hh[2], hh[3]);
            *(uint4*)(dst + 16) = make_uint4(hh[4], hh[5], hh[6], hh[7]);
        }
        __syncthreads();                           // sync2: fp16 A tile ready

        const uint32_t aS = sA16 + (uint32_t)(buf * AF16_BYTES);
        const uint32_t bS = sB + (uint32_t)(st * VC_B_BYTES);

#pragma unroll
        for (int ks = 0; ks < 2; ks++) {
            const int kb = ks * 16;
            uint32_t a[4][4], br[2][4];
#pragma unroll
            for (int mt = 0; mt < 4; mt++)
                ldsm_x4(a[mt][0], a[mt][1], a[mt][2], a[mt][3],
                        aS + aoff[mt] + kb * 2);
#pragma unroll
            for (int nt2 = 0; nt2 < 2; nt2++) {
                int krow = kb + lrow;
                int nc = ((wn + nt2 * 16) >> 3) + bhi;
                int cs = nc ^ (krow & 7);
                ldsm_x4_t(br[nt2][0], br[nt2][1], br[nt2][2], br[nt2][3],
                          bS + (uint32_t)(krow * 128 + cs * 8) * 2);
            }
#pragma unroll
            for (int mt = 0; mt < 4; mt++)
#pragma unroll
                for (int nt = 0; nt < 4; nt++) {
                    int nt2 = nt >> 1, pr = (nt & 1) * 2;
                    mma_f16(acc[mt][nt], a[mt][0], a[mt][1], a[mt][2], a[mt][3],
                            br[nt2][pr], br[nt2][pr + 1]);
                }
        }
    }

#pragma unroll
    for (int mt = 0; mt < 4; mt++) {
        int r0a = row0 + wm + mt * 16 + gid;
#pragma unroll
        for (int nt = 0; nt < 4; nt++) {
            int col = e0 + wn + nt * 8 + 2 * tig;
            __half2 h0 = __floats2half2_rn(acc[mt][nt][0], acc[mt][nt][1]);
            __half2 h1 = __floats2half2_rn(acc[mt][nt][2], acc[mt][nt][3]);
            *(__half2*)(g_vch + (long)r0a * EMB + col) = h0;
            *(__half2*)(g_vch + (long)(r0a + 8) * EMB + col) = h1;
        }
    }
}

// ---------------------------------------------------------------------------
// Masked GEMM (verbatim R11): out = diag(invcnt) * (g_afh @ g_vch) + bo
// BN=256, 512 threads (2m x 8n warps), BK=32, NSTG=4, 1 CTA/SM, grid (4,32).
// ---------------------------------------------------------------------------
#define MS_NSTG 4
#define MS_A_BYTES (BM * 40 * 2)
#define MS_B_BYTES (BK * 256 * 2)
#define MS_SMEM (MS_NSTG * (MS_A_BYTES + MS_B_BYTES))   // 106496

__global__ __launch_bounds__(512, 1) void masked_gemm_kernel(
    const float* __restrict__ bo, float* __restrict__ Y)
{
    extern __shared__ char smh[];
    uint32_t sA = (uint32_t)__cvta_generic_to_shared(smh);
    uint32_t sB = sA + MS_NSTG * MS_A_BYTES;

    const int tid = threadIdx.x;
    const int wid = tid >> 5, lane = tid & 31;
    const int gid = lane >> 2, tig = lane & 3;
    const int wm = (wid >> 3) * 64;
    const int wn = (wid & 7) * 32;

    const int e0 = blockIdx.x * 256;
    const int row0 = blockIdx.y * BM;
    const int n = row0 / SEQ;

    const __half* Ab = g_afh + (long)row0 * SEQ;
    const __half* Bb = g_vch + (long)n * SEQ * EMB + e0;

    const int lrow = lane & 15;
    const int lk8 = (lane & 16) >> 1;
    const int bhi = (lane >> 4) & 1;

    uint32_t aoff[4];
#pragma unroll
    for (int mt = 0; mt < 4; mt++)
        aoff[mt] = (uint32_t)((wm + mt * 16 + lrow) * 40 + lk8) * 2;

    float acc[4][4][4];
#pragma unroll
    for (int a = 0; a < 4; a++)
#pragma unroll
        for (int b = 0; b < 4; b++)
#pragma unroll
            for (int c = 0; c < 4; c++) acc[a][b][c] = 0.f;

    auto load_tiles = [&](int k0, int st) {
        {
            int ch = tid;                           // A: 512 chunks (128 x 4)
            int r = ch >> 2, cc = ch & 3;
            cp16(sA + (uint32_t)(st * MS_A_BYTES) + (uint32_t)(r * 40 + cc * 8) * 2,
                 Ab + (long)r * SEQ + k0 + cc * 8);
        }
#pragma unroll
        for (int u = 0; u < 2; u++) {
            int ch = tid + u * 512;                 // B: 1024 chunks (32 x 32)
            int r = ch >> 5, cc = ch & 31;
            cp16(sB + (uint32_t)(st * MS_B_BYTES) +
                     (uint32_t)(r * 256 + ((cc ^ (r & 7)) * 8)) * 2,
                 Bb + (long)(k0 + r) * EMB + cc * 8);
        }
        cp_commit();
    };

    load_tiles(0, 0);
    load_tiles(BK, 1);
    load_tiles(2 * BK, 2);

    const int nIter = SEQ / BK;
    for (int i = 0; i < nIter; i++) {
        const int rem = nIter - 1 - i;
        if (rem >= 2) cp_wait2();
        else if (rem == 1) cp_wait1();
        else cp_wait0();
        __syncthreads();
        if (i + 3 < nIter) load_tiles((i + 3) * BK, (i + 3) % MS_NSTG);

        const int st = i % MS_NSTG;
        const uint32_t aS = sA + (uint32_t)(st * MS_A_BYTES);
        const uint32_t bS = sB + (uint32_t)(st * MS_B_BYTES);

#pragma unroll
        for (int ks = 0; ks < 2; ks++) {
            const int kb = ks * 16;
            uint32_t a[4][4], br[2][4];
#pragma unroll
            for (int mt = 0; mt < 4; mt++)
                ldsm_x4(a[mt][0], a[mt][1], a[mt][2], a[mt][3],
                        aS + aoff[mt] + kb * 2);
#pragma unroll
            for (int nt2 = 0; nt2 < 2; nt2++) {
                int krow = kb + lrow;
                int nc = ((wn + nt2 * 16) >> 3) + bhi;
                int cs = nc ^ (krow & 7);
                ldsm_x4_t(br[nt2][0], br[nt2][1], br[nt2][2], br[nt2][3],
                          bS + (uint32_t)(krow * 256 + cs * 8) * 2);
            }
#pragma unroll
            for (int mt = 0; mt < 4; mt++)
#pragma unroll
                for (int nt = 0; nt < 4; nt++) {
                    int nt2 = nt >> 1, pr = (nt & 1) * 2;
                    mma_f16(acc[mt][nt], a[mt][0], a[mt][1], a[mt][2], a[mt][3],
                            br[nt2][pr], br[nt2][pr + 1]);
                }
        }
    }

#pragma unroll
    for (int mt = 0; mt < 4; mt++) {
        int r0a = row0 + wm + mt * 16 + gid;
        float s0 = g_invcnt[r0a];
        float s1 = g_invcnt[r0a + 8];
#pragma unroll
        for (int nt = 0; nt < 4; nt++) {
            int col = e0 + wn + nt * 8 + 2 * tig;
            float b0v = bo[col], b1v = bo[col + 1];
            float2 v0 = make_float2(acc[mt][nt][0] * s0 + b0v, acc[mt][nt][1] * s0 + b1v);
            float2 v1 = make_float2(acc[mt][nt][2] * s1 + b0v, acc[mt][nt][3] * s1 + b1v);
            *(float2*)(Y + (long)r0a * EMB + col) = v0;
            *(float2*)(Y + (long)(r0a + 8) * EMB + col) = v1;
        }
    }
}

// ---------------------------------------------------------------------------
extern "C" void kernel_launch(void* const* d_in, const int* in_sizes, int n_in,
                              void* d_out, int out_size)
{
    const float* value = (const float*)d_in[0];
    // key/query/Wk/Wq unused: masked_fill(+1e20) before softmax forces all
    // unmasked scores to underflow; output is the masked average of projected V.
    const int*   mask  = (const int*)d_in[3];
    const float* Wv    = (const float*)d_in[4];
    const float* Wo    = (const float*)d_in[7];
    const float* bo    = (const float*)d_in[8];
    float* out = (float*)d_out;

    cudaFuncSetAttribute(prep_kernel,
                         cudaFuncAttributeMaxDynamicSharedMemorySize, PREP_SMEM);
    cudaFuncSetAttribute(vc_gemm_kernel,
                         cudaFuncAttributeMaxDynamicSharedMemorySize, VC_SMEM);
    cudaFuncSetAttribute(masked_gemm_kernel,
                         cudaFuncAttributeMaxDynamicSharedMemorySize, MS_SMEM);

    prep_kernel<<<PREP_GRID, 256, PREP_SMEM>>>(mask, Wv, Wo);
    {
        dim3 grid(EMB / 128, NROWS / BM);           // (8, 32)
        vc_gemm_kernel<<<grid, 256, VC_SMEM>>>(value);
    }
    {
        dim3 grid(EMB / 256, NROWS / BM);           // (4, 32)
        masked_gemm_kernel<<<grid, 512, MS_SMEM>>>(bo, out);
    }
}